// round 11
// baseline (speedup 1.0000x reference)
#include <cuda_runtime.h>
#include <cuda_fp16.h>
#include <cstdint>
#include <cstddef>

#define VSZ   100000
#define NSEQ  8192
#define SLEN  20

// ---------------------------------------------------------------------------
// Device globals. fp16 packed u32 (two k-consecutive halves). hi plane at
// word offset +0, lo plane at +128 within each 256-word row.
// Gate columns INTERLEAVED: gcol = unit*4 + gate (i,f,g,o).
// h ping-pongs between H0/H1 per step (kills same-launch read/write race).
// ---------------------------------------------------------------------------
__device__ __align__(256) unsigned g_E[(size_t)VSZ * 256];      // 102 MB
__device__ __align__(256) unsigned g_Wih[2048 * 256];           // [dir*1024+gcol][hi|lo]
__device__ __align__(256) unsigned g_Whh[2048 * 256];
__device__ __align__(256) unsigned g_H0[2 * NSEQ * 256];
__device__ __align__(256) unsigned g_H1[2 * NSEQ * 256];
__device__ __align__(256) float    g_c[2 * NSEQ * 256];
__device__ __align__(256) float    g_XG[(size_t)2 * VSZ * 1024];  // 819 MB
__device__ __align__(256) float    g_biasI[2048];
__device__ __align__(256) float    g_part[16 * NSEQ];
__device__ __align__(256) float    g_acc[NSEQ];
__device__ int g_is64;

// ---------------------------------------------------------------------------
__device__ __forceinline__ unsigned pack_split(float a, float b, unsigned& lo) {
    __half ha = __float2half_rn(a), hb = __float2half_rn(b);
    __half la = __float2half_rn(a - __half2float(ha));
    __half lb = __float2half_rn(b - __half2float(hb));
    lo = (unsigned)__half_as_ushort(la) | ((unsigned)__half_as_ushort(lb) << 16);
    return (unsigned)__half_as_ushort(ha) | ((unsigned)__half_as_ushort(hb) << 16);
}

__device__ __forceinline__ uint32_t smem_u32(const void* p) {
    uint32_t a;
    asm("{ .reg .u64 t; cvta.to.shared.u64 t, %1; cvt.u32.u64 %0, t; }" : "=r"(a) : "l"(p));
    return a;
}

__device__ __forceinline__ void cpasync16(uint32_t dst, const void* src) {
    asm volatile("cp.async.cg.shared.global [%0],[%1],16;" :: "r"(dst), "l"(src));
}

#define LDSM4(r, addr) asm volatile( \
    "ldmatrix.sync.aligned.m8n8.x4.shared.b16 {%0,%1,%2,%3},[%4];" \
    : "=r"((r)[0]), "=r"((r)[1]), "=r"((r)[2]), "=r"((r)[3]) : "r"(addr))

#define MMA(d, a, b0, b1) asm volatile( \
    "mma.sync.aligned.m16n8k16.row.col.f32.f16.f16.f32 " \
    "{%0,%1,%2,%3},{%4,%5,%6,%7},{%8,%9},{%0,%1,%2,%3};" \
    : "+f"((d)[0]), "+f"((d)[1]), "+f"((d)[2]), "+f"((d)[3]) \
    : "r"((a)[0]), "r"((a)[1]), "r"((a)[2]), "r"((a)[3]), "r"(b0), "r"(b1))

// ---------------------------------------------------------------------------
__global__ void prep_emb_kernel(const float* __restrict__ emb) {
    size_t i = (size_t)blockIdx.x * blockDim.x + threadIdx.x;
    if (i >= (size_t)VSZ * 128) return;
    size_t v = i >> 7;
    int p = (int)(i & 127);
    unsigned lo;
    unsigned hi = pack_split(emb[v * 256 + 2 * p], emb[v * 256 + 2 * p + 1], lo);
    g_E[v * 256 + p]       = hi;
    g_E[v * 256 + 128 + p] = lo;
}

__global__ void prep_w_kernel(const float* __restrict__ wihf,
                              const float* __restrict__ whhf,
                              const float* __restrict__ wihb,
                              const float* __restrict__ whhb) {
    int i = blockIdx.x * blockDim.x + threadIdx.x;
    if (i >= 2048 * 128) return;
    int dirgcol = i >> 7, kp = i & 127;
    int dir = dirgcol >> 10, gcol = dirgcol & 1023;
    int orow = (gcol & 3) * 256 + (gcol >> 2);
    const float* wih = dir ? wihb : wihf;
    const float* whh = dir ? whhb : whhf;
    unsigned lo, hi;
    hi = pack_split(wih[orow * 256 + 2 * kp], wih[orow * 256 + 2 * kp + 1], lo);
    g_Wih[dirgcol * 256 + kp]       = hi;
    g_Wih[dirgcol * 256 + 128 + kp] = lo;
    hi = pack_split(whh[orow * 256 + 2 * kp], whh[orow * 256 + 2 * kp + 1], lo);
    g_Whh[dirgcol * 256 + kp]       = hi;
    g_Whh[dirgcol * 256 + 128 + kp] = lo;
}

__global__ void prep_state_kernel(const float* __restrict__ bf,
                                  const float* __restrict__ bb,
                                  const void* __restrict__ neigh) {
    int i = blockIdx.x * blockDim.x + threadIdx.x;
    if (i < 2 * NSEQ * 256) { g_H0[i] = 0u; g_H1[i] = 0u; g_c[i] = 0.0f; }
    if (i < 16 * NSEQ)      g_part[i] = 0.0f;
    if (i < 2048) {
        int dir = i >> 10, gcol = i & 1023;
        const float* b = dir ? bb : bf;
        g_biasI[i] = b[(gcol & 3) * 256 + (gcol >> 2)];
    }
    if (i == 0) {
        const long long* p = (const long long*)neigh;
        int ok = 1;
        #pragma unroll
        for (int q = 0; q < 4; q++) {
            long long v = p[q];
            if (v < 0 || v >= (long long)VSZ) ok = 0;
        }
        g_is64 = ok;
    }
}

// ---------------------------------------------------------------------------
// Vocab GEMM: XG[dir][v][gcol] = sum_k emb[v][k]*Wih[dir][gcol][k]
// 128x128, K=256 (8 chunks of 32 halves), cp.async double buffered, 2 CTA/SM.
// MMA product-type is the OUTER loop: same-accumulator reuse distance = 16.
// ---------------------------------------------------------------------------
__global__ __launch_bounds__(256, 2)
void vocab_gemm_kernel() {
    extern __shared__ unsigned sm[];
    const uint32_t smb = smem_u32(sm);
    const int tid = threadIdx.x, lane = tid & 31, warp = tid >> 5;
    const int wr = warp >> 2, wc = warp & 3;
    const int bx = blockIdx.x, by = blockIdx.y;

    const int lrow = tid >> 2, lseg = tid & 3;
    int v0 = by * 128 + lrow, v1 = v0 + 64;
    if (v0 >= VSZ) v0 = VSZ - 1;
    if (v1 >= VSZ) v1 = VSZ - 1;
    const unsigned* pA0 = g_E + (size_t)v0 * 256;
    const unsigned* pA1 = g_E + (size_t)v1 * 256;
    const unsigned* pB0 = g_Wih + (size_t)(bx * 128 + lrow) * 256;
    const unsigned* pB1 = pB0 + 64 * 256;

    const uint32_t dA0 = (uint32_t)(lrow * 20 + lseg * 4) * 4;
    const uint32_t dA1 = dA0 + 64 * 80;
    const uint32_t aLane = (uint32_t)((lane & 15) * 80 + (lane >> 4) * 16);
    const uint32_t bLane = (uint32_t)(((lane & 7) + ((lane >> 4) << 3)) * 80
                                      + (((lane >> 3) & 1) << 4));

    float acc[4][4][4] = {};

    auto load_chunk = [&](int kc, int buf) {
        uint32_t base = smb + (uint32_t)buf * 40960u;
        int kp = kc * 16 + lseg * 4;
        cpasync16(base + dA0,           pA0 + kp);
        cpasync16(base + dA1,           pA1 + kp);
        cpasync16(base + 10240u + dA0,  pA0 + 128 + kp);
        cpasync16(base + 10240u + dA1,  pA1 + 128 + kp);
        cpasync16(base + 20480u + dA0,  pB0 + kp);
        cpasync16(base + 20480u + dA1,  pB1 + kp);
        cpasync16(base + 30720u + dA0,  pB0 + 128 + kp);
        cpasync16(base + 30720u + dA1,  pB1 + 128 + kp);
        asm volatile("cp.async.commit_group;");
    };
    auto compute_chunk = [&](int buf) {
        uint32_t base = smb + (uint32_t)buf * 40960u;
        #pragma unroll
        for (int ks = 0; ks < 2; ks++) {
            uint32_t koff = (uint32_t)ks * 32;
            uint32_t ah[4][4], al[4][4], bh[2][4], bl[2][4];
            #pragma unroll
            for (int mi = 0; mi < 4; mi++) {
                uint32_t ra = base + (uint32_t)(wr * 64 + mi * 16) * 80 + aLane + koff;
                LDSM4(ah[mi], ra);
                LDSM4(al[mi], ra + 10240u);
            }
            #pragma unroll
            for (int np = 0; np < 2; np++) {
                uint32_t rb = base + 20480u + (uint32_t)(wc * 32 + np * 16) * 80 + bLane + koff;
                LDSM4(bh[np], rb);
                LDSM4(bl[np], rb + 10240u);
            }
            // product-type outer: same-acc RAW distance = 16 MMAs
            #pragma unroll
            for (int mi = 0; mi < 4; mi++)
                #pragma unroll
                for (int ni = 0; ni < 4; ni++) {
                    const int np = ni >> 1, s = (ni & 1) * 2;
                    MMA(acc[mi][ni], ah[mi], bh[np][s], bh[np][s + 1]);
                }
            #pragma unroll
            for (int mi = 0; mi < 4; mi++)
                #pragma unroll
                for (int ni = 0; ni < 4; ni++) {
                    const int np = ni >> 1, s = (ni & 1) * 2;
                    MMA(acc[mi][ni], ah[mi], bl[np][s], bl[np][s + 1]);
                }
            #pragma unroll
            for (int mi = 0; mi < 4; mi++)
                #pragma unroll
                for (int ni = 0; ni < 4; ni++) {
                    const int np = ni >> 1, s = (ni & 1) * 2;
                    MMA(acc[mi][ni], al[mi], bh[np][s], bh[np][s + 1]);
                }
        }
    };

    load_chunk(0, 0);
    #pragma unroll 1
    for (int kc = 0; kc < 8; kc++) {
        if (kc < 7) {
            load_chunk(kc + 1, (kc + 1) & 1);
            asm volatile("cp.async.wait_group 1;");
        } else {
            asm volatile("cp.async.wait_group 0;");
        }
        __syncthreads();
        compute_chunk(kc & 1);
        __syncthreads();
    }

    const int dir = bx >> 3;
    #pragma unroll
    for (int mi = 0; mi < 4; mi++) {
        const int r0 = by * 128 + wr * 64 + mi * 16 + (lane >> 2);
        #pragma unroll
        for (int ni = 0; ni < 4; ni++) {
            const int gcol = (bx & 7) * 128 + wc * 32 + ni * 8 + (lane & 3) * 2;
            if (r0 < VSZ)
                *(float2*)(g_XG + ((size_t)dir * VSZ + r0) * 1024 + gcol)
                    = make_float2(acc[mi][ni][0], acc[mi][ni][1]);
            if (r0 + 8 < VSZ)
                *(float2*)(g_XG + ((size_t)dir * VSZ + r0 + 8) * 1024 + gcol)
                    = make_float2(acc[mi][ni][2], acc[mi][ni][3]);
        }
    }
}

// ---------------------------------------------------------------------------
// Step kernel: preact = h @ Whh^T (K=256 split mma), fused epilogue:
// acc -> smem, + XG gather + bias, LSTM pointwise, h repack (ping-pong),
// c update, deterministic per-(dir,bx) partial row sums.
// ---------------------------------------------------------------------------
__global__ __launch_bounds__(256, 2)
void lstm_step_kernel(const void* __restrict__ neigh, int t) {
    extern __shared__ unsigned sm[];
    __shared__ float red[256];
    const uint32_t smb = smem_u32(sm);
    const int tid = threadIdx.x, lane = tid & 31, warp = tid >> 5;
    const int wr = warp >> 2, wc = warp & 3;
    const int bx = blockIdx.x, by = blockIdx.y, dir = blockIdx.z;
    const int t_x = dir ? (SLEN - 1 - t) : t;
    const unsigned* Hin  = (t & 1) ? g_H1 : g_H0;
    unsigned*       Hout = (t & 1) ? g_H0 : g_H1;

    const int prow = tid & 127, phalf = tid >> 7;
    const int pn = by * 128 + prow;
    long long tok;
    if (g_is64) tok = ((const long long*)neigh)[(long long)pn * SLEN + t_x];
    else        tok = ((const int*)neigh)[pn * SLEN + t_x];

    const int lrow = tid >> 2, lseg = tid & 3;
    const int n0 = by * 128 + lrow;
    const unsigned* pA0 = Hin + ((size_t)dir * NSEQ + n0) * 256;
    const unsigned* pA1 = pA0 + 64 * 256;
    const unsigned* pB0 = g_Whh + (size_t)(dir * 1024 + bx * 128 + lrow) * 256;
    const unsigned* pB1 = pB0 + 64 * 256;

    const uint32_t dA0 = (uint32_t)(lrow * 20 + lseg * 4) * 4;
    const uint32_t dA1 = dA0 + 64 * 80;
    const uint32_t aLane = (uint32_t)((lane & 15) * 80 + (lane >> 4) * 16);
    const uint32_t bLane = (uint32_t)(((lane & 7) + ((lane >> 4) << 3)) * 80
                                      + (((lane >> 3) & 1) << 4));

    float acc[4][4][4] = {};

    auto load_chunk = [&](int kc, int buf) {
        uint32_t base = smb + (uint32_t)buf * 40960u;
        int kp = kc * 16 + lseg * 4;
        cpasync16(base + dA0,           pA0 + kp);
        cpasync16(base + dA1,           pA1 + kp);
        cpasync16(base + 10240u + dA0,  pA0 + 128 + kp);
        cpasync16(base + 10240u + dA1,  pA1 + 128 + kp);
        cpasync16(base + 20480u + dA0,  pB0 + kp);
        cpasync16(base + 20480u + dA1,  pB1 + kp);
        cpasync16(base + 30720u + dA0,  pB0 + 128 + kp);
        cpasync16(base + 30720u + dA1,  pB1 + 128 + kp);
        asm volatile("cp.async.commit_group;");
    };
    auto compute_chunk = [&](int buf) {
        uint32_t base = smb + (uint32_t)buf * 40960u;
        #pragma unroll
        for (int ks = 0; ks < 2; ks++) {
            uint32_t koff = (uint32_t)ks * 32;
            uint32_t ah[4][4], al[4][4], bh[2][4], bl[2][4];
            #pragma unroll
            for (int mi = 0; mi < 4; mi++) {
                uint32_t ra = base + (uint32_t)(wr * 64 + mi * 16) * 80 + aLane + koff;
                LDSM4(ah[mi], ra);
                LDSM4(al[mi], ra + 10240u);
            }
            #pragma unroll
            for (int np = 0; np < 2; np++) {
                uint32_t rb = base + 20480u + (uint32_t)(wc * 32 + np * 16) * 80 + bLane + koff;
                LDSM4(bh[np], rb);
                LDSM4(bl[np], rb + 10240u);
            }
            #pragma unroll
            for (int mi = 0; mi < 4; mi++)
                #pragma unroll
                for (int ni = 0; ni < 4; ni++) {
                    const int np = ni >> 1, s = (ni & 1) * 2;
                    MMA(acc[mi][ni], ah[mi], bh[np][s], bh[np][s + 1]);
                }
            #pragma unroll
            for (int mi = 0; mi < 4; mi++)
                #pragma unroll
                for (int ni = 0; ni < 4; ni++) {
                    const int np = ni >> 1, s = (ni & 1) * 2;
                    MMA(acc[mi][ni], ah[mi], bl[np][s], bl[np][s + 1]);
                }
            #pragma unroll
            for (int mi = 0; mi < 4; mi++)
                #pragma unroll
                for (int ni = 0; ni < 4; ni++) {
                    const int np = ni >> 1, s = (ni & 1) * 2;
                    MMA(acc[mi][ni], al[mi], bh[np][s], bh[np][s + 1]);
                }
        }
    };

    load_chunk(0, 0);
    #pragma unroll 1
    for (int kc = 0; kc < 8; kc++) {
        if (kc < 7) {
            load_chunk(kc + 1, (kc + 1) & 1);
            asm volatile("cp.async.wait_group 1;");
        } else {
            asm volatile("cp.async.wait_group 0;");
        }
        __syncthreads();
        compute_chunk(kc & 1);
        __syncthreads();
    }

    // ---- epilogue: acc -> smem (row stride 132 floats) ----
    float* smg = (float*)sm;
    #pragma unroll
    for (int mi = 0; mi < 4; mi++) {
        const int r0 = wr * 64 + mi * 16 + (lane >> 2);
        #pragma unroll
        for (int ni = 0; ni < 4; ni++) {
            const int c = wc * 32 + ni * 8 + (lane & 3) * 2;
            smg[r0 * 132 + c]           = acc[mi][ni][0];
            smg[r0 * 132 + c + 1]       = acc[mi][ni][1];
            smg[(r0 + 8) * 132 + c]     = acc[mi][ni][2];
            smg[(r0 + 8) * 132 + c + 1] = acc[mi][ni][3];
        }
    }
    __syncthreads();

    // ---- pointwise: 2 threads per row, 16 units each ----
    {
        const float4* xg4 = (const float4*)(g_XG
            + ((size_t)dir * VSZ + (size_t)tok) * 1024 + bx * 128 + phalf * 64);
        const float4* bi4 = (const float4*)(g_biasI + dir * 1024 + bx * 128 + phalf * 64);
        float* cp = g_c + ((size_t)dir * NSEQ + pn) * 256 + bx * 32 + phalf * 16;
        unsigned* hp = Hout + ((size_t)dir * NSEQ + pn) * 256 + bx * 16 + phalf * 8;

        float4 cc[4];
        #pragma unroll
        for (int q = 0; q < 4; q++) cc[q] = ((float4*)cp)[q];
        float* ccf = (float*)cc;

        float ssum = 0.0f, hv[16];
        #pragma unroll
        for (int q = 0; q < 16; q++) {
            float4 x = xg4[q];
            float4 bb = bi4[q];
            int c0 = prow * 132 + phalf * 64 + 4 * q;
            float gi = smg[c0 + 0] + x.x + bb.x;
            float gf = smg[c0 + 1] + x.y + bb.y;
            float gg = smg[c0 + 2] + x.z + bb.z;
            float go = smg[c0 + 3] + x.w + bb.w;
            float si = 1.0f / (1.0f + __expf(-gi));
            float sf = 1.0f / (1.0f + __expf(-gf));
            float so = 1.0f / (1.0f + __expf(-go));
            float cn = sf * ccf[q] + si * tanhf(gg);
            float hn = so * tanhf(cn);
            ccf[q] = cn;
            hv[q] = hn;
            ssum += hn;
        }
        #pragma unroll
        for (int q = 0; q < 4; q++) ((float4*)cp)[q] = cc[q];
        #pragma unroll
        for (int w = 0; w < 8; w++) {
            unsigned lo;
            unsigned hi = pack_split(hv[2 * w], hv[2 * w + 1], lo);
            hp[w]       = hi;
            hp[w + 128] = lo;
        }
        red[tid] = ssum;
    }
    __syncthreads();
    if (phalf == 0)
        g_part[(dir * 8 + bx) * NSEQ + pn] += red[tid] + red[tid + 128];
}

// ---------------------------------------------------------------------------
__global__ void final_acc_kernel() {
    int n = blockIdx.x * blockDim.x + threadIdx.x;
    if (n >= NSEQ) return;
    float s = 0.0f;
    #pragma unroll
    for (int p = 0; p < 16; p++) s += g_part[p * NSEQ + n];
    g_acc[n] = s * (1.0f / 512.0f);
}

__global__ void final_bcast_kernel(float* __restrict__ out) {
    int i = blockIdx.x * blockDim.x + threadIdx.x;
    if (i < NSEQ * 512) out[i] = g_acc[i >> 9];
}

// ---------------------------------------------------------------------------
extern "C" void kernel_launch(void* const* d_in, const int* in_sizes, int n_in,
                              void* d_out, int out_size) {
    const float* emb   = (const float*)d_in[0];
    const float* wih_f = (const float*)d_in[1];
    const float* whh_f = (const float*)d_in[2];
    const float* b_f   = (const float*)d_in[3];
    const float* wih_b = (const float*)d_in[4];
    const float* whh_b = (const float*)d_in[5];
    const float* b_b   = (const float*)d_in[6];
    const void*  neigh = d_in[7];
    float* out = (float*)d_out;

    cudaFuncSetAttribute(vocab_gemm_kernel,
                         cudaFuncAttributeMaxDynamicSharedMemorySize, 81920);
    cudaFuncSetAttribute(lstm_step_kernel,
                         cudaFuncAttributeMaxDynamicSharedMemorySize, 81920);

    {
        size_t tot = (size_t)VSZ * 128;
        prep_emb_kernel<<<(unsigned)((tot + 255) / 256), 256>>>(emb);
    }
    prep_w_kernel<<<(2048 * 128 + 255) / 256, 256>>>(wih_f, whh_f, wih_b, whh_b);
    {
        int tot = 2 * NSEQ * 256;
        prep_state_kernel<<<(tot + 255) / 256, 256>>>(b_f, b_b, neigh);
    }

    {
        dim3 grid(16, (VSZ + 127) / 128);   // (16, 782)
        vocab_gemm_kernel<<<grid, 256, 81920>>>();
    }

    dim3 sgrid(8, NSEQ / 128, 2);           // (8, 64, 2)
    for (int t = 0; t < SLEN; t++)
        lstm_step_kernel<<<sgrid, 256, 81920>>>(neigh, t);

    final_acc_kernel<<<(NSEQ + 255) / 256, 256>>>();
    final_bcast_kernel<<<(NSEQ * 512 + 255) / 256, 256>>>(out);
}

// round 12
// speedup vs baseline: 1.1551x; 1.1551x over previous
#include <cuda_runtime.h>
#include <cuda_fp16.h>
#include <cstdint>
#include <cstddef>

#define VSZ   100000
#define NSEQ  8192
#define SLEN  20

// ---------------------------------------------------------------------------
// Device globals. fp16 packed u32 (two k-consecutive halves). hi plane at
// word offset +0, lo plane at +128 within each 256-word row.
// Gate columns INTERLEAVED: gcol = unit*4 + gate (i,f,g,o).
// h ping-pongs between H0/H1 per step. h stored fp16 (hi only) — the
// recurrence GEMM uses 2-product split (weights split, h plain fp16).
// ---------------------------------------------------------------------------
__device__ __align__(256) unsigned g_E[(size_t)VSZ * 256];      // 102 MB
__device__ __align__(256) unsigned g_Wih[2048 * 256];           // [dir*1024+gcol][hi|lo]
__device__ __align__(256) unsigned g_Whh[2048 * 256];
__device__ __align__(256) unsigned g_H0[2 * NSEQ * 256];
__device__ __align__(256) unsigned g_H1[2 * NSEQ * 256];
__device__ __align__(256) float    g_c[2 * NSEQ * 256];
__device__ __align__(256) float    g_XG[(size_t)2 * VSZ * 1024];  // 819 MB
__device__ __align__(256) float    g_biasI[2048];
__device__ __align__(256) float    g_part[16 * NSEQ];
__device__ __align__(256) float    g_acc[NSEQ];
__device__ int g_is64;

// ---------------------------------------------------------------------------
__device__ __forceinline__ unsigned pack_split(float a, float b, unsigned& lo) {
    __half ha = __float2half_rn(a), hb = __float2half_rn(b);
    __half la = __float2half_rn(a - __half2float(ha));
    __half lb = __float2half_rn(b - __half2float(hb));
    lo = (unsigned)__half_as_ushort(la) | ((unsigned)__half_as_ushort(lb) << 16);
    return (unsigned)__half_as_ushort(ha) | ((unsigned)__half_as_ushort(hb) << 16);
}

__device__ __forceinline__ uint32_t smem_u32(const void* p) {
    uint32_t a;
    asm("{ .reg .u64 t; cvta.to.shared.u64 t, %1; cvt.u32.u64 %0, t; }" : "=r"(a) : "l"(p));
    return a;
}

__device__ __forceinline__ void cpasync16(uint32_t dst, const void* src) {
    asm volatile("cp.async.cg.shared.global [%0],[%1],16;" :: "r"(dst), "l"(src));
}

#define LDSM4(r, addr) asm volatile( \
    "ldmatrix.sync.aligned.m8n8.x4.shared.b16 {%0,%1,%2,%3},[%4];" \
    : "=r"((r)[0]), "=r"((r)[1]), "=r"((r)[2]), "=r"((r)[3]) : "r"(addr))

#define MMA(d, a, b0, b1) asm volatile( \
    "mma.sync.aligned.m16n8k16.row.col.f32.f16.f16.f32 " \
    "{%0,%1,%2,%3},{%4,%5,%6,%7},{%8,%9},{%0,%1,%2,%3};" \
    : "+f"((d)[0]), "+f"((d)[1]), "+f"((d)[2]), "+f"((d)[3]) \
    : "r"((a)[0]), "r"((a)[1]), "r"((a)[2]), "r"((a)[3]), "r"(b0), "r"(b1))

// ---------------------------------------------------------------------------
__global__ void prep_emb_kernel(const float* __restrict__ emb) {
    size_t i = (size_t)blockIdx.x * blockDim.x + threadIdx.x;
    if (i >= (size_t)VSZ * 128) return;
    size_t v = i >> 7;
    int p = (int)(i & 127);
    unsigned lo;
    unsigned hi = pack_split(emb[v * 256 + 2 * p], emb[v * 256 + 2 * p + 1], lo);
    g_E[v * 256 + p]       = hi;
    g_E[v * 256 + 128 + p] = lo;
}

__global__ void prep_w_kernel(const float* __restrict__ wihf,
                              const float* __restrict__ whhf,
                              const float* __restrict__ wihb,
                              const float* __restrict__ whhb) {
    int i = blockIdx.x * blockDim.x + threadIdx.x;
    if (i >= 2048 * 128) return;
    int dirgcol = i >> 7, kp = i & 127;
    int dir = dirgcol >> 10, gcol = dirgcol & 1023;
    int orow = (gcol & 3) * 256 + (gcol >> 2);
    const float* wih = dir ? wihb : wihf;
    const float* whh = dir ? whhb : whhf;
    unsigned lo, hi;
    hi = pack_split(wih[orow * 256 + 2 * kp], wih[orow * 256 + 2 * kp + 1], lo);
    g_Wih[dirgcol * 256 + kp]       = hi;
    g_Wih[dirgcol * 256 + 128 + kp] = lo;
    hi = pack_split(whh[orow * 256 + 2 * kp], whh[orow * 256 + 2 * kp + 1], lo);
    g_Whh[dirgcol * 256 + kp]       = hi;
    g_Whh[dirgcol * 256 + 128 + kp] = lo;
}

__global__ void prep_state_kernel(const float* __restrict__ bf,
                                  const float* __restrict__ bb,
                                  const void* __restrict__ neigh) {
    int i = blockIdx.x * blockDim.x + threadIdx.x;
    if (i < 2 * NSEQ * 256) { g_H0[i] = 0u; g_H1[i] = 0u; g_c[i] = 0.0f; }
    if (i < 16 * NSEQ)      g_part[i] = 0.0f;
    if (i < 2048) {
        int dir = i >> 10, gcol = i & 1023;
        const float* b = dir ? bb : bf;
        g_biasI[i] = b[(gcol & 3) * 256 + (gcol >> 2)];
    }
    if (i == 0) {
        const long long* p = (const long long*)neigh;
        int ok = 1;
        #pragma unroll
        for (int q = 0; q < 4; q++) {
            long long v = p[q];
            if (v < 0 || v >= (long long)VSZ) ok = 0;
        }
        g_is64 = ok;
    }
}

// ---------------------------------------------------------------------------
// Vocab GEMM: XG[dir][v][gcol] = sum_k emb[v][k]*Wih[dir][gcol][k]
// 128x128, K=256 (8 chunks of 32 halves), 3-product split, 2 CTA/SM,
// single-barrier double-buffered mainloop.
// ---------------------------------------------------------------------------
__global__ __launch_bounds__(256, 2)
void vocab_gemm_kernel() {
    extern __shared__ unsigned sm[];
    const uint32_t smb = smem_u32(sm);
    const int tid = threadIdx.x, lane = tid & 31, warp = tid >> 5;
    const int wr = warp >> 2, wc = warp & 3;
    const int bx = blockIdx.x, by = blockIdx.y;

    const int lrow = tid >> 2, lseg = tid & 3;
    int v0 = by * 128 + lrow, v1 = v0 + 64;
    if (v0 >= VSZ) v0 = VSZ - 1;
    if (v1 >= VSZ) v1 = VSZ - 1;
    const unsigned* pA0 = g_E + (size_t)v0 * 256;
    const unsigned* pA1 = g_E + (size_t)v1 * 256;
    const unsigned* pB0 = g_Wih + (size_t)(bx * 128 + lrow) * 256;
    const unsigned* pB1 = pB0 + 64 * 256;

    const uint32_t dA0 = (uint32_t)(lrow * 20 + lseg * 4) * 4;
    const uint32_t dA1 = dA0 + 64 * 80;
    const uint32_t aLane = (uint32_t)((lane & 15) * 80 + (lane >> 4) * 16);
    const uint32_t bLane = (uint32_t)(((lane & 7) + ((lane >> 4) << 3)) * 80
                                      + (((lane >> 3) & 1) << 4));

    float acc[4][4][4] = {};

    auto load_chunk = [&](int kc, int buf) {
        uint32_t base = smb + (uint32_t)buf * 40960u;
        int kp = kc * 16 + lseg * 4;
        cpasync16(base + dA0,           pA0 + kp);
        cpasync16(base + dA1,           pA1 + kp);
        cpasync16(base + 10240u + dA0,  pA0 + 128 + kp);
        cpasync16(base + 10240u + dA1,  pA1 + 128 + kp);
        cpasync16(base + 20480u + dA0,  pB0 + kp);
        cpasync16(base + 20480u + dA1,  pB1 + kp);
        cpasync16(base + 30720u + dA0,  pB0 + 128 + kp);
        cpasync16(base + 30720u + dA1,  pB1 + 128 + kp);
        asm volatile("cp.async.commit_group;");
    };
    auto compute_chunk = [&](int buf) {
        uint32_t base = smb + (uint32_t)buf * 40960u;
        #pragma unroll
        for (int ks = 0; ks < 2; ks++) {
            uint32_t koff = (uint32_t)ks * 32;
            uint32_t ah[4][4], al[4][4], bh[2][4], bl[2][4];
            #pragma unroll
            for (int mi = 0; mi < 4; mi++) {
                uint32_t ra = base + (uint32_t)(wr * 64 + mi * 16) * 80 + aLane + koff;
                LDSM4(ah[mi], ra);
                LDSM4(al[mi], ra + 10240u);
            }
            #pragma unroll
            for (int np = 0; np < 2; np++) {
                uint32_t rb = base + 20480u + (uint32_t)(wc * 32 + np * 16) * 80 + bLane + koff;
                LDSM4(bh[np], rb);
                LDSM4(bl[np], rb + 10240u);
            }
            #pragma unroll
            for (int mi = 0; mi < 4; mi++)
                #pragma unroll
                for (int ni = 0; ni < 4; ni++) {
                    const int np = ni >> 1, s = (ni & 1) * 2;
                    MMA(acc[mi][ni], ah[mi], bh[np][s], bh[np][s + 1]);
                    MMA(acc[mi][ni], ah[mi], bl[np][s], bl[np][s + 1]);
                    MMA(acc[mi][ni], al[mi], bh[np][s], bh[np][s + 1]);
                }
        }
    };

    // single-barrier mainloop: wait(all); sync(proves loads visible AND
    // compute(kc-1) done on the buffer load(kc+1) overwrites); load; compute.
    load_chunk(0, 0);
    #pragma unroll 1
    for (int kc = 0; kc < 8; kc++) {
        asm volatile("cp.async.wait_group 0;");
        __syncthreads();
        if (kc < 7) load_chunk(kc + 1, (kc + 1) & 1);
        compute_chunk(kc & 1);
    }

    const int dir = bx >> 3;
    #pragma unroll
    for (int mi = 0; mi < 4; mi++) {
        const int r0 = by * 128 + wr * 64 + mi * 16 + (lane >> 2);
        #pragma unroll
        for (int ni = 0; ni < 4; ni++) {
            const int gcol = (bx & 7) * 128 + wc * 32 + ni * 8 + (lane & 3) * 2;
            if (r0 < VSZ)
                *(float2*)(g_XG + ((size_t)dir * VSZ + r0) * 1024 + gcol)
                    = make_float2(acc[mi][ni][0], acc[mi][ni][1]);
            if (r0 + 8 < VSZ)
                *(float2*)(g_XG + ((size_t)dir * VSZ + r0 + 8) * 1024 + gcol)
                    = make_float2(acc[mi][ni][2], acc[mi][ni][3]);
        }
    }
}

// ---------------------------------------------------------------------------
// Step kernel: preact = h @ Whh^T. 2-PRODUCT split: h plain fp16 (hi only),
// weights hi/lo split -> products hh*wh + hh*wl. Fused LSTM epilogue.
// ---------------------------------------------------------------------------
__global__ __launch_bounds__(256, 2)
void lstm_step_kernel(const void* __restrict__ neigh, int t) {
    extern __shared__ unsigned sm[];
    __shared__ float red[256];
    const uint32_t smb = smem_u32(sm);
    const int tid = threadIdx.x, lane = tid & 31, warp = tid >> 5;
    const int wr = warp >> 2, wc = warp & 3;
    const int bx = blockIdx.x, by = blockIdx.y, dir = blockIdx.z;
    const int t_x = dir ? (SLEN - 1 - t) : t;
    const unsigned* Hin  = (t & 1) ? g_H1 : g_H0;
    unsigned*       Hout = (t & 1) ? g_H0 : g_H1;

    const int prow = tid & 127, phalf = tid >> 7;
    const int pn = by * 128 + prow;
    long long tok;
    if (g_is64) tok = ((const long long*)neigh)[(long long)pn * SLEN + t_x];
    else        tok = ((const int*)neigh)[pn * SLEN + t_x];

    const int lrow = tid >> 2, lseg = tid & 3;
    const int n0 = by * 128 + lrow;
    const unsigned* pA0 = Hin + ((size_t)dir * NSEQ + n0) * 256;
    const unsigned* pA1 = pA0 + 64 * 256;
    const unsigned* pB0 = g_Whh + (size_t)(dir * 1024 + bx * 128 + lrow) * 256;
    const unsigned* pB1 = pB0 + 64 * 256;

    const uint32_t dA0 = (uint32_t)(lrow * 20 + lseg * 4) * 4;
    const uint32_t dA1 = dA0 + 64 * 80;
    const uint32_t aLane = (uint32_t)((lane & 15) * 80 + (lane >> 4) * 16);
    const uint32_t bLane = (uint32_t)(((lane & 7) + ((lane >> 4) << 3)) * 80
                                      + (((lane >> 3) & 1) << 4));

    float acc[4][4][4] = {};

    auto load_chunk = [&](int kc, int buf) {
        uint32_t base = smb + (uint32_t)buf * 40960u;
        int kp = kc * 16 + lseg * 4;
        cpasync16(base + dA0,           pA0 + kp);
        cpasync16(base + dA1,           pA1 + kp);
        cpasync16(base + 20480u + dA0,  pB0 + kp);
        cpasync16(base + 20480u + dA1,  pB1 + kp);
        cpasync16(base + 30720u + dA0,  pB0 + 128 + kp);
        cpasync16(base + 30720u + dA1,  pB1 + 128 + kp);
        asm volatile("cp.async.commit_group;");
    };
    auto compute_chunk = [&](int buf) {
        uint32_t base = smb + (uint32_t)buf * 40960u;
        #pragma unroll
        for (int ks = 0; ks < 2; ks++) {
            uint32_t koff = (uint32_t)ks * 32;
            uint32_t ah[4][4], bh[2][4], bl[2][4];
            #pragma unroll
            for (int mi = 0; mi < 4; mi++) {
                uint32_t ra = base + (uint32_t)(wr * 64 + mi * 16) * 80 + aLane + koff;
                LDSM4(ah[mi], ra);
            }
            #pragma unroll
            for (int np = 0; np < 2; np++) {
                uint32_t rb = base + 20480u + (uint32_t)(wc * 32 + np * 16) * 80 + bLane + koff;
                LDSM4(bh[np], rb);
                LDSM4(bl[np], rb + 10240u);
            }
            #pragma unroll
            for (int mi = 0; mi < 4; mi++)
                #pragma unroll
                for (int ni = 0; ni < 4; ni++) {
                    const int np = ni >> 1, s = (ni & 1) * 2;
                    MMA(acc[mi][ni], ah[mi], bh[np][s], bh[np][s + 1]);
                    MMA(acc[mi][ni], ah[mi], bl[np][s], bl[np][s + 1]);
                }
        }
    };

    load_chunk(0, 0);
    #pragma unroll 1
    for (int kc = 0; kc < 8; kc++) {
        asm volatile("cp.async.wait_group 0;");
        __syncthreads();
        if (kc < 7) load_chunk(kc + 1, (kc + 1) & 1);
        compute_chunk(kc & 1);
    }

    // ---- epilogue: acc -> smem (row stride 132 floats) ----
    __syncthreads();   // mainloop's trailing compute has no barrier after it
    float* smg = (float*)sm;
    #pragma unroll
    for (int mi = 0; mi < 4; mi++) {
        const int r0 = wr * 64 + mi * 16 + (lane >> 2);
        #pragma unroll
        for (int ni = 0; ni < 4; ni++) {
            const int c = wc * 32 + ni * 8 + (lane & 3) * 2;
            smg[r0 * 132 + c]           = acc[mi][ni][0];
            smg[r0 * 132 + c + 1]       = acc[mi][ni][1];
            smg[(r0 + 8) * 132 + c]     = acc[mi][ni][2];
            smg[(r0 + 8) * 132 + c + 1] = acc[mi][ni][3];
        }
    }
    __syncthreads();

    // ---- pointwise: 2 threads per row, 16 units each ----
    {
        const float4* xg4 = (const float4*)(g_XG
            + ((size_t)dir * VSZ + (size_t)tok) * 1024 + bx * 128 + phalf * 64);
        const float4* bi4 = (const float4*)(g_biasI + dir * 1024 + bx * 128 + phalf * 64);
        float* cp = g_c + ((size_t)dir * NSEQ + pn) * 256 + bx * 32 + phalf * 16;
        unsigned* hp = Hout + ((size_t)dir * NSEQ + pn) * 256 + bx * 16 + phalf * 8;

        float4 cc[4];
        #pragma unroll
        for (int q = 0; q < 4; q++) cc[q] = ((float4*)cp)[q];
        float* ccf = (float*)cc;

        float ssum = 0.0f, hv[16];
        #pragma unroll
        for (int q = 0; q < 16; q++) {
            float4 x = xg4[q];
            float4 bb = bi4[q];
            int c0 = prow * 132 + phalf * 64 + 4 * q;
            float gi = smg[c0 + 0] + x.x + bb.x;
            float gf = smg[c0 + 1] + x.y + bb.y;
            float gg = smg[c0 + 2] + x.z + bb.z;
            float go = smg[c0 + 3] + x.w + bb.w;
            float si = 1.0f / (1.0f + __expf(-gi));
            float sf = 1.0f / (1.0f + __expf(-gf));
            float so = 1.0f / (1.0f + __expf(-go));
            float cn = sf * ccf[q] + si * tanhf(gg);
            float hn = so * tanhf(cn);
            ccf[q] = cn;
            hv[q] = hn;
            ssum += hn;
        }
        #pragma unroll
        for (int q = 0; q < 4; q++) ((float4*)cp)[q] = cc[q];
        // h stored fp16 (hi only) — lo plane unused by the 2-product GEMM
        #pragma unroll
        for (int w = 0; w < 8; w++) {
            __half h0 = __float2half_rn(hv[2 * w]);
            __half h1 = __float2half_rn(hv[2 * w + 1]);
            hp[w] = (unsigned)__half_as_ushort(h0)
                  | ((unsigned)__half_as_ushort(h1) << 16);
        }
        red[tid] = ssum;
    }
    __syncthreads();
    if (phalf == 0)
        g_part[(dir * 8 + bx) * NSEQ + pn] += red[tid] + red[tid + 128];
}

// ---------------------------------------------------------------------------
__global__ void final_acc_kernel() {
    int n = blockIdx.x * blockDim.x + threadIdx.x;
    if (n >= NSEQ) return;
    float s = 0.0f;
    #pragma unroll
    for (int p = 0; p < 16; p++) s += g_part[p * NSEQ + n];
    g_acc[n] = s * (1.0f / 512.0f);
}

__global__ void final_bcast_kernel(float* __restrict__ out) {
    int i = blockIdx.x * blockDim.x + threadIdx.x;
    if (i < NSEQ * 512) out[i] = g_acc[i >> 9];
}

// ---------------------------------------------------------------------------
extern "C" void kernel_launch(void* const* d_in, const int* in_sizes, int n_in,
                              void* d_out, int out_size) {
    const float* emb   = (const float*)d_in[0];
    const float* wih_f = (const float*)d_in[1];
    const float* whh_f = (const float*)d_in[2];
    const float* b_f   = (const float*)d_in[3];
    const float* wih_b = (const float*)d_in[4];
    const float* whh_b = (const float*)d_in[5];
    const float* b_b   = (const float*)d_in[6];
    const void*  neigh = d_in[7];
    float* out = (float*)d_out;

    cudaFuncSetAttribute(vocab_gemm_kernel,
                         cudaFuncAttributeMaxDynamicSharedMemorySize, 81920);
    cudaFuncSetAttribute(lstm_step_kernel,
                         cudaFuncAttributeMaxDynamicSharedMemorySize, 81920);

    {
        size_t tot = (size_t)VSZ * 128;
        prep_emb_kernel<<<(unsigned)((tot + 255) / 256), 256>>>(emb);
    }
    prep_w_kernel<<<(2048 * 128 + 255) / 256, 256>>>(wih_f, whh_f, wih_b, whh_b);
    {
        int tot = 2 * NSEQ * 256;
        prep_state_kernel<<<(tot + 255) / 256, 256>>>(b_f, b_b, neigh);
    }

    {
        dim3 grid(16, (VSZ + 127) / 128);   // (16, 782)
        vocab_gemm_kernel<<<grid, 256, 81920>>>();
    }

    dim3 sgrid(8, NSEQ / 128, 2);           // (8, 64, 2)
    for (int t = 0; t < SLEN; t++)
        lstm_step_kernel<<<sgrid, 256, 81920>>>(neigh, t);

    final_acc_kernel<<<(NSEQ + 255) / 256, 256>>>();
    final_bcast_kernel<<<(NSEQ * 512 + 255) / 256, 256>>>(out);
}

// round 15
// speedup vs baseline: 1.2979x; 1.1236x over previous
#include <cuda_runtime.h>
#include <cuda_fp16.h>
#include <cstdint>
#include <cstddef>

#define VSZ   100000
#define NSEQ  8192
#define SLEN  20

// ---------------------------------------------------------------------------
// Device globals. fp16 packed u32 (two k-consecutive halves).
// g_E: hi-only rows of 128 words (2-product vocab GEMM needs no emb-lo).
// g_Wih/g_Whh: hi plane words [0,128), lo plane [128,256) per row.
// Gate columns INTERLEAVED: gcol = unit*4 + gate (i,f,g,o).
// g_XG16: gate preacts in fp16 half2 words [dir][v][512 words].
// h ping-pongs H0/H1 per step, stored plain fp16.
// ---------------------------------------------------------------------------
__device__ __align__(256) unsigned g_E[(size_t)VSZ * 128];       // 51 MB
__device__ __align__(256) unsigned g_Wih[2048 * 256];
__device__ __align__(256) unsigned g_Whh[2048 * 256];
__device__ __align__(256) unsigned g_H0[2 * NSEQ * 256];
__device__ __align__(256) unsigned g_H1[2 * NSEQ * 256];
__device__ __align__(256) float    g_c[2 * NSEQ * 256];
__device__ __align__(256) unsigned g_XG16[(size_t)2 * VSZ * 512]; // 410 MB
__device__ __align__(256) float    g_biasI[2048];
__device__ __align__(256) float    g_part[16 * NSEQ];
__device__ __align__(256) float    g_acc[NSEQ];
__device__ int g_is64;

// ---------------------------------------------------------------------------
__device__ __forceinline__ unsigned pack_split(float a, float b, unsigned& lo) {
    __half ha = __float2half_rn(a), hb = __float2half_rn(b);
    __half la = __float2half_rn(a - __half2float(ha));
    __half lb = __float2half_rn(b - __half2float(hb));
    lo = (unsigned)__half_as_ushort(la) | ((unsigned)__half_as_ushort(lb) << 16);
    return (unsigned)__half_as_ushort(ha) | ((unsigned)__half_as_ushort(hb) << 16);
}

__device__ __forceinline__ unsigned pack_h2(float a, float b) {
    __half h0 = __float2half_rn(a), h1 = __float2half_rn(b);
    return (unsigned)__half_as_ushort(h0) | ((unsigned)__half_as_ushort(h1) << 16);
}

__device__ __forceinline__ uint32_t smem_u32(const void* p) {
    uint32_t a;
    asm("{ .reg .u64 t; cvta.to.shared.u64 t, %1; cvt.u32.u64 %0, t; }" : "=r"(a) : "l"(p));
    return a;
}

__device__ __forceinline__ void cpasync16(uint32_t dst, const void* src) {
    asm volatile("cp.async.cg.shared.global [%0],[%1],16;" :: "r"(dst), "l"(src));
}

#define LDSM4(r, addr) asm volatile( \
    "ldmatrix.sync.aligned.m8n8.x4.shared.b16 {%0,%1,%2,%3},[%4];" \
    : "=r"((r)[0]), "=r"((r)[1]), "=r"((r)[2]), "=r"((r)[3]) : "r"(addr))

#define MMA(d, a, b0, b1) asm volatile( \
    "mma.sync.aligned.m16n8k16.row.col.f32.f16.f16.f32 " \
    "{%0,%1,%2,%3},{%4,%5,%6,%7},{%8,%9},{%0,%1,%2,%3};" \
    : "+f"((d)[0]), "+f"((d)[1]), "+f"((d)[2]), "+f"((d)[3]) \
    : "r"((a)[0]), "r"((a)[1]), "r"((a)[2]), "r"((a)[3]), "r"(b0), "r"(b1))

// ---------------------------------------------------------------------------
__global__ void prep_emb_kernel(const float* __restrict__ emb) {
    size_t i = (size_t)blockIdx.x * blockDim.x + threadIdx.x;
    if (i >= (size_t)VSZ * 128) return;
    size_t v = i >> 7;
    int p = (int)(i & 127);
    g_E[i] = pack_h2(emb[v * 256 + 2 * p], emb[v * 256 + 2 * p + 1]);
}

__global__ void prep_w_kernel(const float* __restrict__ wihf,
                              const float* __restrict__ whhf,
                              const float* __restrict__ wihb,
                              const float* __restrict__ whhb) {
    int i = blockIdx.x * blockDim.x + threadIdx.x;
    if (i >= 2048 * 128) return;
    int dirgcol = i >> 7, kp = i & 127;
    int dir = dirgcol >> 10, gcol = dirgcol & 1023;
    int orow = (gcol & 3) * 256 + (gcol >> 2);
    const float* wih = dir ? wihb : wihf;
    const float* whh = dir ? whhb : whhf;
    unsigned lo, hi;
    hi = pack_split(wih[orow * 256 + 2 * kp], wih[orow * 256 + 2 * kp + 1], lo);
    g_Wih[dirgcol * 256 + kp]       = hi;
    g_Wih[dirgcol * 256 + 128 + kp] = lo;
    hi = pack_split(whh[orow * 256 + 2 * kp], whh[orow * 256 + 2 * kp + 1], lo);
    g_Whh[dirgcol * 256 + kp]       = hi;
    g_Whh[dirgcol * 256 + 128 + kp] = lo;
}

__global__ void prep_state_kernel(const float* __restrict__ bf,
                                  const float* __restrict__ bb,
                                  const void* __restrict__ neigh) {
    int i = blockIdx.x * blockDim.x + threadIdx.x;
    if (i < 2 * NSEQ * 256) { g_H0[i] = 0u; g_H1[i] = 0u; g_c[i] = 0.0f; }
    if (i < 16 * NSEQ)      g_part[i] = 0.0f;
    if (i < 2048) {
        int dir = i >> 10, gcol = i & 1023;
        const float* b = dir ? bb : bf;
        g_biasI[i] = b[(gcol & 3) * 256 + (gcol >> 2)];
    }
    if (i == 0) {
        const long long* p = (const long long*)neigh;
        int ok = 1;
        #pragma unroll
        for (int q = 0; q < 4; q++) {
            long long v = p[q];
            if (v < 0 || v >= (long long)VSZ) ok = 0;
        }
        g_is64 = ok;
    }
}

// ---------------------------------------------------------------------------
// Vocab GEMM (2-product): XG[dir][v][gcol] = sum_k emb16[v][k]*Wih[gcol][k]
// products: e_hi*w_hi + e_hi*w_lo. 128x128, K=256 (8 chunks), 2 CTA/SM,
// single-barrier double-buffered mainloop. Epilogue stores half2.
// ---------------------------------------------------------------------------
__global__ __launch_bounds__(256, 2)
void vocab_gemm_kernel() {
    extern __shared__ unsigned sm[];
    const uint32_t smb = smem_u32(sm);
    const int tid = threadIdx.x, lane = tid & 31, warp = tid >> 5;
    const int wr = warp >> 2, wc = warp & 3;
    const int bx = blockIdx.x, by = blockIdx.y;

    const int lrow = tid >> 2, lseg = tid & 3;
    int v0 = by * 128 + lrow, v1 = v0 + 64;
    if (v0 >= VSZ) v0 = VSZ - 1;
    if (v1 >= VSZ) v1 = VSZ - 1;
    const unsigned* pA0 = g_E + (size_t)v0 * 128;
    const unsigned* pA1 = g_E + (size_t)v1 * 128;
    const unsigned* pB0 = g_Wih + (size_t)(bx * 128 + lrow) * 256;
    const unsigned* pB1 = pB0 + 64 * 256;

    const uint32_t dA0 = (uint32_t)(lrow * 20 + lseg * 4) * 4;
    const uint32_t dA1 = dA0 + 64 * 80;
    const uint32_t aLane = (uint32_t)((lane & 15) * 80 + (lane >> 4) * 16);
    const uint32_t bLane = (uint32_t)(((lane & 7) + ((lane >> 4) << 3)) * 80
                                      + (((lane >> 3) & 1) << 4));

    float acc[4][4][4] = {};

    auto load_chunk = [&](int kc, int buf) {
        uint32_t base = smb + (uint32_t)buf * 40960u;
        int kp = kc * 16 + lseg * 4;
        cpasync16(base + dA0,           pA0 + kp);
        cpasync16(base + dA1,           pA1 + kp);
        cpasync16(base + 20480u + dA0,  pB0 + kp);
        cpasync16(base + 20480u + dA1,  pB1 + kp);
        cpasync16(base + 30720u + dA0,  pB0 + 128 + kp);
        cpasync16(base + 30720u + dA1,  pB1 + 128 + kp);
        asm volatile("cp.async.commit_group;");
    };
    auto compute_chunk = [&](int buf) {
        uint32_t base = smb + (uint32_t)buf * 40960u;
        #pragma unroll
        for (int ks = 0; ks < 2; ks++) {
            uint32_t koff = (uint32_t)ks * 32;
            uint32_t ah[4][4], bh[2][4], bl[2][4];
            #pragma unroll
            for (int mi = 0; mi < 4; mi++) {
                uint32_t ra = base + (uint32_t)(wr * 64 + mi * 16) * 80 + aLane + koff;
                LDSM4(ah[mi], ra);
            }
            #pragma unroll
            for (int np = 0; np < 2; np++) {
                uint32_t rb = base + 20480u + (uint32_t)(wc * 32 + np * 16) * 80 + bLane + koff;
                LDSM4(bh[np], rb);
                LDSM4(bl[np], rb + 10240u);
            }
            #pragma unroll
            for (int mi = 0; mi < 4; mi++)
                #pragma unroll
                for (int ni = 0; ni < 4; ni++) {
                    const int np = ni >> 1, s = (ni & 1) * 2;
                    MMA(acc[mi][ni], ah[mi], bh[np][s], bh[np][s + 1]);
                    MMA(acc[mi][ni], ah[mi], bl[np][s], bl[np][s + 1]);
                }
        }
    };

    load_chunk(0, 0);
    #pragma unroll 1
    for (int kc = 0; kc < 8; kc++) {
        asm volatile("cp.async.wait_group 0;");
        __syncthreads();
        if (kc < 7) load_chunk(kc + 1, (kc + 1) & 1);
        compute_chunk(kc & 1);
    }

    const int dir = bx >> 3;
    #pragma unroll
    for (int mi = 0; mi < 4; mi++) {
        const int r0 = by * 128 + wr * 64 + mi * 16 + (lane >> 2);
        #pragma unroll
        for (int ni = 0; ni < 4; ni++) {
            const int gcol = (bx & 7) * 128 + wc * 32 + ni * 8 + (lane & 3) * 2;
            unsigned w0 = pack_h2(acc[mi][ni][0], acc[mi][ni][1]);
            unsigned w1 = pack_h2(acc[mi][ni][2], acc[mi][ni][3]);
            if (r0 < VSZ)
                g_XG16[((size_t)dir * VSZ + r0) * 512 + (gcol >> 1)] = w0;
            if (r0 + 8 < VSZ)
                g_XG16[((size_t)dir * VSZ + r0 + 8) * 512 + (gcol >> 1)] = w1;
        }
    }
}

// ---------------------------------------------------------------------------
// Step kernel: preact = h @ Whh^T, 2-product split, fused LSTM epilogue
// with fp16 XG gather.
// ---------------------------------------------------------------------------
__global__ __launch_bounds__(256, 2)
void lstm_step_kernel(const void* __restrict__ neigh, int t) {
    extern __shared__ unsigned sm[];
    __shared__ float red[256];
    const uint32_t smb = smem_u32(sm);
    const int tid = threadIdx.x, lane = tid & 31, warp = tid >> 5;
    const int wr = warp >> 2, wc = warp & 3;
    const int bx = blockIdx.x, by = blockIdx.y, dir = blockIdx.z;
    const int t_x = dir ? (SLEN - 1 - t) : t;
    const unsigned* Hin  = (t & 1) ? g_H1 : g_H0;
    unsigned*       Hout = (t & 1) ? g_H0 : g_H1;

    const int prow = tid & 127, phalf = tid >> 7;
    const int pn = by * 128 + prow;
    long long tok;
    if (g_is64) tok = ((const long long*)neigh)[(long long)pn * SLEN + t_x];
    else        tok = ((const int*)neigh)[pn * SLEN + t_x];

    const int lrow = tid >> 2, lseg = tid & 3;
    const int n0 = by * 128 + lrow;
    const unsigned* pA0 = Hin + ((size_t)dir * NSEQ + n0) * 256;
    const unsigned* pA1 = pA0 + 64 * 256;
    const unsigned* pB0 = g_Whh + (size_t)(dir * 1024 + bx * 128 + lrow) * 256;
    const unsigned* pB1 = pB0 + 64 * 256;

    const uint32_t dA0 = (uint32_t)(lrow * 20 + lseg * 4) * 4;
    const uint32_t dA1 = dA0 + 64 * 80;
    const uint32_t aLane = (uint32_t)((lane & 15) * 80 + (lane >> 4) * 16);
    const uint32_t bLane = (uint32_t)(((lane & 7) + ((lane >> 4) << 3)) * 80
                                      + (((lane >> 3) & 1) << 4));

    float acc[4][4][4] = {};

    auto load_chunk = [&](int kc, int buf) {
        uint32_t base = smb + (uint32_t)buf * 40960u;
        int kp = kc * 16 + lseg * 4;
        cpasync16(base + dA0,           pA0 + kp);
        cpasync16(base + dA1,           pA1 + kp);
        cpasync16(base + 20480u + dA0,  pB0 + kp);
        cpasync16(base + 20480u + dA1,  pB1 + kp);
        cpasync16(base + 30720u + dA0,  pB0 + 128 + kp);
        cpasync16(base + 30720u + dA1,  pB1 + 128 + kp);
        asm volatile("cp.async.commit_group;");
    };
    auto compute_chunk = [&](int buf) {
        uint32_t base = smb + (uint32_t)buf * 40960u;
        #pragma unroll
        for (int ks = 0; ks < 2; ks++) {
            uint32_t koff = (uint32_t)ks * 32;
            uint32_t ah[4][4], bh[2][4], bl[2][4];
            #pragma unroll
            for (int mi = 0; mi < 4; mi++) {
                uint32_t ra = base + (uint32_t)(wr * 64 + mi * 16) * 80 + aLane + koff;
                LDSM4(ah[mi], ra);
            }
            #pragma unroll
            for (int np = 0; np < 2; np++) {
                uint32_t rb = base + 20480u + (uint32_t)(wc * 32 + np * 16) * 80 + bLane + koff;
                LDSM4(bh[np], rb);
                LDSM4(bl[np], rb + 10240u);
            }
            #pragma unroll
            for (int mi = 0; mi < 4; mi++)
                #pragma unroll
                for (int ni = 0; ni < 4; ni++) {
                    const int np = ni >> 1, s = (ni & 1) * 2;
                    MMA(acc[mi][ni], ah[mi], bh[np][s], bh[np][s + 1]);
                    MMA(acc[mi][ni], ah[mi], bl[np][s], bl[np][s + 1]);
                }
        }
    };

    load_chunk(0, 0);
    #pragma unroll 1
    for (int kc = 0; kc < 8; kc++) {
        asm volatile("cp.async.wait_group 0;");
        __syncthreads();
        if (kc < 7) load_chunk(kc + 1, (kc + 1) & 1);
        compute_chunk(kc & 1);
    }

    // ---- epilogue: acc -> smem (row stride 132 floats) ----
    __syncthreads();
    float* smg = (float*)sm;
    #pragma unroll
    for (int mi = 0; mi < 4; mi++) {
        const int r0 = wr * 64 + mi * 16 + (lane >> 2);
        #pragma unroll
        for (int ni = 0; ni < 4; ni++) {
            const int c = wc * 32 + ni * 8 + (lane & 3) * 2;
            smg[r0 * 132 + c]           = acc[mi][ni][0];
            smg[r0 * 132 + c + 1]       = acc[mi][ni][1];
            smg[(r0 + 8) * 132 + c]     = acc[mi][ni][2];
            smg[(r0 + 8) * 132 + c + 1] = acc[mi][ni][3];
        }
    }
    __syncthreads();

    // ---- pointwise: 2 threads per row, 16 units each; fp16 XG gather ----
    {
        const uint4* xgv = (const uint4*)(g_XG16
            + ((size_t)dir * VSZ + (size_t)tok) * 512 + bx * 64 + phalf * 32);
        const float4* bi4 = (const float4*)(g_biasI + dir * 1024 + bx * 128 + phalf * 64);
        float* cp = g_c + ((size_t)dir * NSEQ + pn) * 256 + bx * 32 + phalf * 16;
        unsigned* hp = Hout + ((size_t)dir * NSEQ + pn) * 256 + bx * 16 + phalf * 8;

        unsigned xw[32];
        #pragma unroll
        for (int q = 0; q < 8; q++) ((uint4*)xw)[q] = xgv[q];

        float4 cc[4];
        #pragma unroll
        for (int q = 0; q < 4; q++) cc[q] = ((float4*)cp)[q];
        float* ccf = (float*)cc;

        float ssum = 0.0f, hv[16];
        #pragma unroll
        for (int q = 0; q < 16; q++) {
            float2 x01 = __half22float2(*(const __half2*)&xw[2 * q]);
            float2 x23 = __half22float2(*(const __half2*)&xw[2 * q + 1]);
            float4 bb = bi4[q];
            int c0 = prow * 132 + phalf * 64 + 4 * q;
            float gi = smg[c0 + 0] + x01.x + bb.x;
            float gf = smg[c0 + 1] + x01.y + bb.y;
            float gg = smg[c0 + 2] + x23.x + bb.z;
            float go = smg[c0 + 3] + x23.y + bb.w;
            float si = 1.0f / (1.0f + __expf(-gi));
            float sf = 1.0f / (1.0f + __expf(-gf));
            float so = 1.0f / (1.0f + __expf(-go));
            float cn = sf * ccf[q] + si * tanhf(gg);
            float hn = so * tanhf(cn);
            ccf[q] = cn;
            hv[q] = hn;
            ssum += hn;
        }
        #pragma unroll
        for (int q = 0; q < 4; q++) ((float4*)cp)[q] = cc[q];
        #pragma unroll
        for (int w = 0; w < 8; w++)
            hp[w] = pack_h2(hv[2 * w], hv[2 * w + 1]);
        red[tid] = ssum;
    }
    __syncthreads();
    if (phalf == 0)
        g_part[(dir * 8 + bx) * NSEQ + pn] += red[tid] + red[tid + 128];
}

// ---------------------------------------------------------------------------
__global__ void final_acc_kernel() {
    int n = blockIdx.x * blockDim.x + threadIdx.x;
    if (n >= NSEQ) return;
    float s = 0.0f;
    #pragma unroll
    for (int p = 0; p < 16; p++) s += g_part[p * NSEQ + n];
    g_acc[n] = s * (1.0f / 512.0f);
}

__global__ void final_bcast_kernel(float* __restrict__ out) {
    int i = blockIdx.x * blockDim.x + threadIdx.x;
    if (i < NSEQ * 512) out[i] = g_acc[i >> 9];
}

// ---------------------------------------------------------------------------
extern "C" void kernel_launch(void* const* d_in, const int* in_sizes, int n_in,
                              void* d_out, int out_size) {
    const float* emb   = (const float*)d_in[0];
    const float* wih_f = (const float*)d_in[1];
    const float* whh_f = (const float*)d_in[2];
    const float* b_f   = (const float*)d_in[3];
    const float* wih_b = (const float*)d_in[4];
    const float* whh_b = (const float*)d_in[5];
    const float* b_b   = (const float*)d_in[6];
    const void*  neigh = d_in[7];
    float* out = (float*)d_out;

    cudaFuncSetAttribute(vocab_gemm_kernel,
                         cudaFuncAttributeMaxDynamicSharedMemorySize, 81920);
    cudaFuncSetAttribute(lstm_step_kernel,
                         cudaFuncAttributeMaxDynamicSharedMemorySize, 81920);

    {
        size_t tot = (size_t)VSZ * 128;
        prep_emb_kernel<<<(unsigned)((tot + 255) / 256), 256>>>(emb);
    }
    prep_w_kernel<<<(2048 * 128 + 255) / 256, 256>>>(wih_f, whh_f, wih_b, whh_b);
    {
        int tot = 2 * NSEQ * 256;
        prep_state_kernel<<<(tot + 255) / 256, 256>>>(b_f, b_b, neigh);
    }

    {
        dim3 grid(16, (VSZ + 127) / 128);   // (16, 782)
        vocab_gemm_kernel<<<grid, 256, 81920>>>();
    }

    dim3 sgrid(8, NSEQ / 128, 2);           // (8, 64, 2)
    for (int t = 0; t < SLEN; t++)
        lstm_step_kernel<<<sgrid, 256, 81920>>>(neigh, t);

    final_acc_kernel<<<(NSEQ + 255) / 256, 256>>>();
    final_bcast_kernel<<<(NSEQ * 512 + 255) / 256, 256>>>(out);
}